// round 16
// baseline (speedup 1.0000x reference)
#include <cuda_runtime.h>
#include <cuda_bf16.h>
#include <math.h>
#include <stdint.h>

#ifndef M_PI
#define M_PI 3.14159265358979323846
#endif

#define BATCH 128
#define HH    256
#define CC    10
#define MATSZ (HH*HH)
#define DEG   9                   /* monomial degree; PS s=3: 4 matrix mults */

// ---- smem layout (bytes). 528-stride rows -> conflict-free ldmatrix. ----
#define YROW    528
#define YH_OFF  0
#define B_HI    135168            /* 256*528 */
#define B_LO    (B_HI + 64*528)
#define SMEM_TOTAL (B_HI + 2*64*528)      /* 202752 */

#define NTHR 512

// ---------------- scratch ----------------------------------------------------
__device__ __align__(16) __nv_bfloat16 g_Yh  [BATCH*MATSZ];
__device__ __align__(16) __nv_bfloat16 g_Yl  [BATCH*MATSZ];
__device__ __align__(16) __nv_bfloat16 g_Ylp [BATCH*MATSZ];   // fragment-major
__device__ __align__(16) __nv_bfloat16 g_Y2h [BATCH*MATSZ];
__device__ __align__(16) __nv_bfloat16 g_Y2l [BATCH*MATSZ];
__device__ __align__(16) __nv_bfloat16 g_Y3h [BATCH*MATSZ];
__device__ __align__(16) __nv_bfloat16 g_Y3l [BATCH*MATSZ];
__device__ __align__(16) __nv_bfloat16 g_Y3lp[BATCH*MATSZ];   // fragment-major
__device__ float g_B2[BATCH*MATSZ];   // a9*Y3 + a6 I + a7 Y + a8 Y2
__device__ float g_B1[BATCH*MATSZ];   // a3 I + a4 Y + a5 Y2
__device__ float g_B0[BATCH*MATSZ];   // a0 I + a1 Y + a2 Y2
__device__ float g_F [BATCH*MATSZ];
__device__ float g_Ws[CC*MATSZ];
__device__ float g_center[MATSZ];
__device__ float g_P [CC*MATSZ];
__device__ float g_acc;

struct HArgs { float a[DEG+1]; };

// ---------------- PTX helpers ------------------------------------------------
__device__ __forceinline__ uint32_t smem_u32(const void* p) {
    uint32_t a;
    asm("{ .reg .u64 t; cvta.to.shared.u64 t, %1; cvt.u32.u64 %0, t; }"
        : "=r"(a) : "l"(p));
    return a;
}
__device__ __forceinline__ void cpasync16(uint32_t dst, const void* src) {
    asm volatile("cp.async.cg.shared.global [%0], [%1], 16;"
                 :: "r"(dst), "l"(src) : "memory");
}
__device__ __forceinline__ void cp_commit() {
    asm volatile("cp.async.commit_group;" ::: "memory");
}
template<int N> __device__ __forceinline__ void cp_wait() {
    asm volatile("cp.async.wait_group %0;" :: "n"(N) : "memory");
}
__device__ __forceinline__ void ldsm4(uint32_t& r0, uint32_t& r1,
                                      uint32_t& r2, uint32_t& r3, uint32_t a) {
    asm volatile("ldmatrix.sync.aligned.m8n8.x4.shared.b16 {%0,%1,%2,%3}, [%4];"
                 : "=r"(r0), "=r"(r1), "=r"(r2), "=r"(r3) : "r"(a));
}
__device__ __forceinline__ void mma16816(float* c, const uint32_t* a,
                                         uint32_t b0, uint32_t b1) {
    asm volatile(
        "mma.sync.aligned.m16n8k16.row.col.f32.bf16.bf16.f32 "
        "{%0,%1,%2,%3}, {%4,%5,%6,%7}, {%8,%9}, {%0,%1,%2,%3};"
        : "+f"(c[0]), "+f"(c[1]), "+f"(c[2]), "+f"(c[3])
        : "r"(a[0]), "r"(a[1]), "r"(a[2]), "r"(a[3]), "r"(b0), "r"(b1));
}
__device__ __forceinline__ uint32_t split2(float v0, float v1, uint32_t& lo) {
    __nv_bfloat16 h0 = __float2bfloat16(v0);
    __nv_bfloat16 l0 = __float2bfloat16(v0 - __bfloat162float(h0));
    __nv_bfloat16 h1 = __float2bfloat16(v1);
    __nv_bfloat16 l1 = __float2bfloat16(v1 - __bfloat162float(h1));
    lo = (uint32_t)__bfloat16_as_ushort(l0) | ((uint32_t)__bfloat16_as_ushort(l1) << 16);
    return (uint32_t)__bfloat16_as_ushort(h0) | ((uint32_t)__bfloat16_as_ushort(h1) << 16);
}
__device__ __forceinline__ float pair_sum(uint32_t h, uint32_t l, int sel) {
    unsigned short hu = sel ? (unsigned short)(h >> 16) : (unsigned short)(h & 0xffff);
    unsigned short lu = sel ? (unsigned short)(l >> 16) : (unsigned short)(l & 0xffff);
    return __bfloat162float(__ushort_as_bfloat16(hu)) +
           __bfloat162float(__ushort_as_bfloat16(lu));
}

// ---------------- shared mult k-loop (barrier-free, 16x64 warp tile) ---------
// A-lo fragment-major with NEXT-KC REGISTER PREFETCH: the uint4 for kc+1 is
// loaded at the top of iteration kc, so L2 latency is off the MMA path.
__device__ __forceinline__ void mult_kloop(
    const char* dsm, uint32_t aAhi, uint32_t aB,
    const uint4* __restrict__ Aperm, int w, int lane,
    float (&acc)[8][4])
{
    const int abase = w*32 + lane;
    uint4 av = __ldg(Aperm + abase);                  // kc = 0
    #pragma unroll 4
    for (int kc = 0; kc < 16; ++kc) {
        uint4 avn;
        if (kc < 15) avn = __ldg(Aperm + ((kc + 1)*512 + abase));
        const uint32_t kb = (uint32_t)(kc << 5);
        uint32_t ah[4], al[4];
        ldsm4(ah[0], ah[1], ah[2], ah[3], aAhi + kb);
        al[0] = av.x;  al[1] = av.y;  al[2] = av.z;  al[3] = av.w;
        #pragma unroll
        for (int np = 0; np < 4; ++np) {
            uint32_t a = aB + (uint32_t)(np*16*YROW) + kb;
            uint32_t bh0, bh1, bh2, bh3, bl0, bl1, bl2, bl3;
            ldsm4(bh0, bh1, bh2, bh3, a);
            ldsm4(bl0, bl1, bl2, bl3, a + (uint32_t)(64*YROW));
            mma16816(acc[2*np+0], ah, bh0, bh2);
            mma16816(acc[2*np+1], ah, bh1, bh3);
            mma16816(acc[2*np+0], ah, bl0, bl2);
            mma16816(acc[2*np+1], ah, bl1, bl3);
            mma16816(acc[2*np+0], al, bh0, bh2);
            mma16816(acc[2*np+1], al, bh1, bh3);
        }
        av = avn;
    }
}

// ---------------- prep: Y = s*X + o*I, split hi/lo (+ perm lo copy) ---------
__global__ void prep_mats(const float* __restrict__ X, float s, float o) {
    unsigned gid = blockIdx.x * blockDim.x + threadIdx.x;
    float4 x = ((const float4*)X)[gid];
    unsigned within = gid & (MATSZ/4 - 1);
    int i  = (int)(within >> 6);
    int j0 = (int)(within & 63) << 2;

    float y[4];
    y[0] = s*x.x + ((i==j0+0)?o:0.f);  y[1] = s*x.y + ((i==j0+1)?o:0.f);
    y[2] = s*x.z + ((i==j0+2)?o:0.f);  y[3] = s*x.w + ((i==j0+3)?o:0.f);

    unsigned hh[4], ll[4];
    #pragma unroll
    for (int q = 0; q < 4; ++q) {
        __nv_bfloat16 h = __float2bfloat16(y[q]);
        __nv_bfloat16 l = __float2bfloat16(y[q] - __bfloat162float(h));
        hh[q] = __bfloat16_as_ushort(h);
        ll[q] = __bfloat16_as_ushort(l);
    }
    uint32_t w0 = ll[0] | (ll[1]<<16);
    uint32_t w1 = ll[2] | (ll[3]<<16);
    ((uint2*)g_Yh)[gid] = make_uint2(hh[0] | (hh[1]<<16), hh[2] | (hh[3]<<16));
    ((uint2*)g_Yl)[gid] = make_uint2(w0, w1);

    // fragment-major copy of Y-lo
    {
        int m    = (int)(gid >> 14);            // matrix index (MATSZ/4 = 16384)
        int kc   = j0 >> 4;
        int band = i >> 4;
        int sub  = i & 7;
        int hi8  = (i >> 3) & 1;
        int khi  = (j0 >> 3) & 1;
        int lq0  = (j0 >> 1) & 3;               // even: 0 or 2
        int j    = hi8 + (khi << 1);
        uint32_t* Yp = (uint32_t*)g_Ylp + (size_t)m * (MATSZ/2);
        uint32_t base = (uint32_t)(((kc*16 + band)*32 + ((sub<<2) | lq0))*4 + j);
        Yp[base]     = w0;
        Yp[base + 4] = w1;                      // lq0+1 -> +4 words
    }
    if (gid == 0) g_acc = 0.f;
}

__global__ void prep_W(const float* __restrict__ W) {
    int gid = blockIdx.x * blockDim.x + threadIdx.x;
    int c   = gid >> 16;
    int rem = gid & 65535;
    int i   = rem >> 8, j = rem & 255;
    g_Ws[gid] = 0.5f * (W[gid] + W[(c<<16) + (j<<8) + i]);
    if (gid < MATSZ) g_center[gid] = 0.f;       // zero for center atomics
}

// ---------------- pow phase: Y2 = Y*Y, Y3 = Y*Y2 -----------------------------
__global__ void __launch_bounds__(NTHR, 1) pow_kernel() {
    extern __shared__ char dsm[];
    const uint32_t sb = smem_u32(dsm);

    const int slice = blockIdx.x, b = blockIdx.y;
    const int tid = threadIdx.x, w = tid >> 5, lane = tid & 31;
    const int laneA = lane & 15, laneHi = (lane >> 4) << 4;
    const int n0g = slice << 6;
    const size_t moff = (size_t)b * MATSZ;
    const char* Yh = (const char*)(g_Yh + moff);

    // A resident = Yh; B init = Y[:, slice] (Y symmetric -> rows)
    #pragma unroll
    for (int i = 0; i < 16; ++i) {
        int op = tid + (i << 9);
        int r = op >> 5, ch = (op & 31) << 4;
        cpasync16(sb + YH_OFF + r*YROW + ch, Yh + r*512 + ch);
    }
    {
        const char* Yl = (const char*)(g_Yl + moff);
        #pragma unroll
        for (int i = 0; i < 4; ++i) {
            int op = tid + (i << 9);
            int n = op >> 5, ch = (op & 31) << 4;
            cpasync16(sb + B_HI + n*YROW + ch, Yh + (size_t)(n0g + n)*512 + ch);
            cpasync16(sb + B_LO + n*YROW + ch, Yl + (size_t)(n0g + n)*512 + ch);
        }
    }
    cp_commit();
    cp_wait<0>();
    __syncthreads();

    const uint32_t aAhi = sb + YH_OFF + (w*16 + laneA)*YROW + laneHi;
    const uint32_t aB   = sb + B_HI + laneA*YROW + laneHi;
    const uint4* Aperm  = (const uint4*)g_Ylp + (moff >> 3);

    #pragma unroll 1
    for (int step = 0; step < 2; ++step) {
        float acc[8][4];
        #pragma unroll
        for (int nt = 0; nt < 8; ++nt)
            #pragma unroll
            for (int q = 0; q < 4; ++q) acc[nt][q] = 0.f;

        mult_kloop(dsm, aAhi, aB, Aperm, w, lane, acc);
        __syncthreads();

        uint32_t* gh = (uint32_t*)((step == 0 ? g_Y2h : g_Y3h) + moff);
        uint32_t* gl = (uint32_t*)((step == 0 ? g_Y2l : g_Y3l) + moff);
        uint32_t* Yp = (uint32_t*)g_Y3lp + (moff >> 1);
        const bool toSmem = (step < 1);

        #pragma unroll
        for (int nt = 0; nt < 8; ++nt)
            #pragma unroll
            for (int hrow = 0; hrow < 2; ++hrow) {
                int r  = w*16 + (lane >> 2) + hrow*8;
                int c0 = nt*8 + ((lane & 3) << 1);
                float v0 = acc[nt][2*hrow], v1 = acc[nt][2*hrow+1];
                uint32_t lo, hi = split2(v0, v1, lo);
                uint32_t off = (uint32_t)(r*256 + n0g + c0);
                gh[off >> 1] = hi;
                gl[off >> 1] = lo;
                if (toSmem) {
                    *(uint16_t*)(dsm + B_HI + c0*YROW + r*2)     = (uint16_t)(hi & 0xffff);
                    *(uint16_t*)(dsm + B_HI + (c0+1)*YROW + r*2) = (uint16_t)(hi >> 16);
                    *(uint16_t*)(dsm + B_LO + c0*YROW + r*2)     = (uint16_t)(lo & 0xffff);
                    *(uint16_t*)(dsm + B_LO + (c0+1)*YROW + r*2) = (uint16_t)(lo >> 16);
                } else {
                    // fragment-major Y3-lo for horner's A operand
                    int slot = (((n0g >> 4) + (nt >> 1))*16 + w)*32 + lane;
                    Yp[slot*4 + (hrow + ((nt & 1) << 1))] = lo;
                }
            }
        __syncthreads();
    }
}

// ---------------- bterms: B2f / B1 / B0 (fp32, coalesced, once) -------------
__global__ void bterms_kernel(HArgs ha) {
    unsigned gid = blockIdx.x * blockDim.x + threadIdx.x;   // float4 group
    unsigned within = gid & (MATSZ/4 - 1);
    int i  = (int)(within >> 6);
    int j0 = (int)(within & 63) << 2;

    uint2 yh = ((const uint2*)g_Yh )[gid], yl = ((const uint2*)g_Yl )[gid];
    uint2 h2 = ((const uint2*)g_Y2h)[gid], l2 = ((const uint2*)g_Y2l)[gid];
    uint2 h3 = ((const uint2*)g_Y3h)[gid], l3 = ((const uint2*)g_Y3l)[gid];

    float b2[4], b1[4], b0[4];
    #pragma unroll
    for (int q = 0; q < 4; ++q) {
        int sel = q & 1;
        float y  = pair_sum(q < 2 ? yh.x : yh.y, q < 2 ? yl.x : yl.y, sel);
        float y2 = pair_sum(q < 2 ? h2.x : h2.y, q < 2 ? l2.x : l2.y, sel);
        float y3 = pair_sum(q < 2 ? h3.x : h3.y, q < 2 ? l3.x : l3.y, sel);
        float id = (i == j0 + q) ? 1.f : 0.f;
        b2[q] = ha.a[9]*y3 + ha.a[6]*id + ha.a[7]*y + ha.a[8]*y2;
        b1[q] = ha.a[3]*id + ha.a[4]*y + ha.a[5]*y2;
        b0[q] = ha.a[0]*id + ha.a[1]*y + ha.a[2]*y2;
    }
    ((float4*)g_B2)[gid] = make_float4(b2[0], b2[1], b2[2], b2[3]);
    ((float4*)g_B1)[gid] = make_float4(b1[0], b1[1], b1[2], b1[3]);
    ((float4*)g_B0)[gid] = make_float4(b0[0], b0[1], b0[2], b0[3]);
}

// ---------------- horner phase: C0 = B2f; C1 = Y3*C0 + B1; F = Y3*C1 + B0 ---
__global__ void __launch_bounds__(NTHR, 1) horner_kernel() {
    extern __shared__ char dsm[];
    const uint32_t sb = smem_u32(dsm);

    const int slice = blockIdx.x, b = blockIdx.y;
    const int tid = threadIdx.x, w = tid >> 5, lane = tid & 31;
    const int laneA = lane & 15, laneHi = (lane >> 4) << 4;
    const int n0g = slice << 6;
    const size_t moff = (size_t)b * MATSZ;

    // A resident = Y3 hi
    {
        const char* A = (const char*)(g_Y3h + moff);
        #pragma unroll
        for (int i = 0; i < 16; ++i) {
            int op = tid + (i << 9);
            int r = op >> 5, ch = (op & 31) << 4;
            cpasync16(sb + YH_OFF + r*YROW + ch, A + r*512 + ch);
        }
        cp_commit();
    }

    // C init: rows (n0g+nl) of C0 = B2f (coalesced fp32 load, split to bf16)
    {
        const float* B2 = g_B2 + moff;
        #pragma unroll 4
        for (int i = 0; i < 16; ++i) {
            int e  = tid + (i << 9);
            int nl = e >> 7;
            int k2 = (e & 127) << 1;
            float2 v = *(const float2*)(B2 + (size_t)(n0g + nl)*256 + k2);
            uint32_t lo, hi = split2(v.x, v.y, lo);
            *(uint32_t*)(dsm + B_HI + nl*YROW + k2*2) = hi;
            *(uint32_t*)(dsm + B_LO + nl*YROW + k2*2) = lo;
        }
    }
    cp_wait<0>();
    __syncthreads();

    const uint32_t aAhi = sb + YH_OFF + (w*16 + laneA)*YROW + laneHi;
    const uint32_t aB   = sb + B_HI + laneA*YROW + laneHi;
    const uint4* Aperm  = (const uint4*)g_Y3lp + (moff >> 3);

    // ---- mult 1: C1 = Y3*C0 + B1 ----
    {
        float acc[8][4];
        #pragma unroll
        for (int nt = 0; nt < 8; ++nt)
            #pragma unroll
            for (int q = 0; q < 4; ++q) acc[nt][q] = 0.f;
        mult_kloop(dsm, aAhi, aB, Aperm, w, lane, acc);
        __syncthreads();
        const float* B1 = g_B1 + moff;
        #pragma unroll
        for (int nt = 0; nt < 8; ++nt)
            #pragma unroll
            for (int hrow = 0; hrow < 2; ++hrow) {
                int r  = w*16 + (lane >> 2) + hrow*8;
                int c0 = nt*8 + ((lane & 3) << 1);
                float2 bv = *(const float2*)(B1 + (size_t)r*256 + n0g + c0);
                float v0 = acc[nt][2*hrow]   + bv.x;
                float v1 = acc[nt][2*hrow+1] + bv.y;
                uint32_t lo, hi = split2(v0, v1, lo);
                *(uint16_t*)(dsm + B_HI + c0*YROW + r*2)     = (uint16_t)(hi & 0xffff);
                *(uint16_t*)(dsm + B_HI + (c0+1)*YROW + r*2) = (uint16_t)(hi >> 16);
                *(uint16_t*)(dsm + B_LO + c0*YROW + r*2)     = (uint16_t)(lo & 0xffff);
                *(uint16_t*)(dsm + B_LO + (c0+1)*YROW + r*2) = (uint16_t)(lo >> 16);
            }
        __syncthreads();
    }

    // ---- mult 2: F = Y3*C1 + B0 (write gmem) ----
    {
        float acc[8][4];
        #pragma unroll
        for (int nt = 0; nt < 8; ++nt)
            #pragma unroll
            for (int q = 0; q < 4; ++q) acc[nt][q] = 0.f;
        mult_kloop(dsm, aAhi, aB, Aperm, w, lane, acc);

        const float* B0 = g_B0 + moff;
        float* Fm = g_F + moff;
        #pragma unroll
        for (int nt = 0; nt < 8; ++nt)
            #pragma unroll
            for (int hrow = 0; hrow < 2; ++hrow) {
                int r  = w*16 + (lane >> 2) + hrow*8;
                int c0 = nt*8 + ((lane & 3) << 1);
                float2 bv = *(const float2*)(B0 + (size_t)r*256 + n0g + c0);
                *(float2*)(Fm + (size_t)r*256 + n0g + c0) =
                    make_float2(acc[nt][2*hrow] + bv.x, acc[nt][2*hrow+1] + bv.y);
            }
    }
}

// ---------------- tails ------------------------------------------------------
// center: 4-way batch split, float2, atomic accumulate (g_center zeroed in prep_W)
__global__ void center_kernel() {
    int p  = blockIdx.x * blockDim.x + threadIdx.x;   // float2 index 0..32767
    int b0 = blockIdx.y << 5;                          // batch quarter * 32
    float sx = 0.f, sy = 0.f;
    #pragma unroll 4
    for (int i = 0; i < 32; ++i) {
        float2 v = ((const float2*)(g_F + (size_t)(b0 + i)*MATSZ))[p];
        sx += v.x;  sy += v.y;
    }
    const float inv = 1.f / BATCH;
    atomicAdd(&g_center[2*p],     sx * inv);
    atomicAdd(&g_center[2*p + 1], sy * inv);
}

__global__ void out_kernel(float* __restrict__ out) {
    int b = blockIdx.x;
    const float4* F4 = (const float4*)(g_F + (size_t)b*MATSZ);
    float acc[CC];
    #pragma unroll
    for (int c = 0; c < CC; ++c) acc[c] = 0.f;
    for (int t = threadIdx.x; t < MATSZ/4; t += 256) {
        float4 f = F4[t];
        #pragma unroll
        for (int c = 0; c < CC; ++c) {
            float4 w = ((const float4*)(g_Ws + (size_t)c*MATSZ))[t];
            acc[c] += f.x*w.x + f.y*w.y + f.z*w.z + f.w*w.w;
        }
    }
    __shared__ float red[8][CC];
    #pragma unroll
    for (int c = 0; c < CC; ++c) {
        float v = acc[c];
        #pragma unroll
        for (int o = 16; o; o >>= 1) v += __shfl_down_sync(0xffffffffu, v, o);
        if ((threadIdx.x & 31) == 0) red[threadIdx.x >> 5][c] = v;
    }
    __syncthreads();
    if (threadIdx.x < CC) {
        float v = 0.f;
        #pragma unroll
        for (int w = 0; w < 8; ++w) v += red[w][threadIdx.x];
        out[b*CC + threadIdx.x] = v;
    }
}

__global__ void p_kernel() {
    int c  = blockIdx.y;
    int r0 = blockIdx.x * 32;
    __shared__ float Wb[32][256];
    for (int l = 0; l < 32; ++l)
        Wb[l][threadIdx.x] = g_Ws[(size_t)c*MATSZ + (size_t)(r0+l)*256 + threadIdx.x];
    __syncthreads();
    int j = threadIdx.x;
    float acc[32];
    #pragma unroll
    for (int ii = 0; ii < 32; ++ii) acc[ii] = 0.f;
    for (int k = 0; k < 256; ++k) {
        float bv = g_center[k*256 + j];
        #pragma unroll
        for (int ii = 0; ii < 32; ++ii) acc[ii] += Wb[ii][k] * bv;
    }
    for (int ii = 0; ii < 32; ++ii)
        g_P[(size_t)c*MATSZ + (size_t)(r0+ii)*256 + j] = acc[ii];
}

__global__ void g_kernel() {
    int c = blockIdx.x;
    const float* P = g_P + (size_t)c*MATSZ;
    float acc = 0.f;
    for (int idx = threadIdx.x; idx < MATSZ; idx += 256) {
        int i = idx >> 8, j = idx & 255;
        acc += P[idx] * P[j*256 + i];
    }
    __shared__ float red[8];
    #pragma unroll
    for (int o = 16; o; o >>= 1) acc += __shfl_down_sync(0xffffffffu, acc, o);
    if ((threadIdx.x & 31) == 0) red[threadIdx.x >> 5] = acc;
    __syncthreads();
    if (threadIdx.x < 8) {
        float v = red[threadIdx.x];
        #pragma unroll
        for (int o = 4; o; o >>= 1) v += __shfl_down_sync(0xffu, v, o);
        if (threadIdx.x == 0) atomicAdd(&g_acc, v);
    }
}

__global__ void fin_kernel(float* __restrict__ out, int out_size) {
    out[out_size - 1] = g_acc * (1.f / CC);
}

// ---------------- host -------------------------------------------------------
extern "C" void kernel_launch(void* const* d_in, const int* in_sizes, int n_in,
                              void* d_out, int out_size) {
    const float* X = (const float*)d_in[0];
    const float* W = (const float*)d_in[1];
    float* out = (float*)d_out;

    const double a = 0.98, bb = 5.4;
    double coef[DEG+1];
    {
        const int N = 128;
        for (int k = 0; k <= DEG; ++k) {
            double s = 0.0;
            for (int j = 0; j < N; ++j) {
                double th  = M_PI * (j + 0.5) / N;
                double lam = 0.5*(bb+a) + 0.5*(bb-a)*cos(th);
                s += log(lam) * cos(k*th);
            }
            coef[k] = 2.0 / N * s;
        }
        coef[0] *= 0.5;
    }
    // Chebyshev -> monomial (safe: rho = 2.48 > 2)
    double tc[DEG+1][DEG+1] = {};
    tc[0][0] = 1.0;
    tc[1][1] = 1.0;
    for (int k = 2; k <= DEG; ++k)
        for (int j = 0; j <= k; ++j)
            tc[k][j] = (j ? 2.0*tc[k-1][j-1] : 0.0) - tc[k-2][j];
    double am[DEG+1] = {};
    for (int k = 0; k <= DEG; ++k)
        for (int j = 0; j <= k; ++j)
            am[j] += coef[k] * tc[k][j];

    const float sc = (float)( 2.0/(bb-a));
    const float of = (float)(-(bb+a)/(bb-a));
    HArgs ha;
    for (int j = 0; j <= DEG; ++j) ha.a[j] = (float)am[j];

    cudaFuncSetAttribute(pow_kernel,    cudaFuncAttributeMaxDynamicSharedMemorySize, SMEM_TOTAL);
    cudaFuncSetAttribute(horner_kernel, cudaFuncAttributeMaxDynamicSharedMemorySize, SMEM_TOTAL);

    prep_mats<<<(BATCH*MATSZ/4)/256, 256>>>(X, sc, of);
    prep_W<<<(CC*MATSZ)/256, 256>>>(W);
    pow_kernel<<<dim3(4, BATCH), NTHR, SMEM_TOTAL>>>();
    bterms_kernel<<<(BATCH*MATSZ/4)/256, 256>>>(ha);
    horner_kernel<<<dim3(4, BATCH), NTHR, SMEM_TOTAL>>>();
    center_kernel<<<dim3(128, 4), 256>>>();
    out_kernel<<<BATCH, 256>>>(out);
    p_kernel<<<dim3(8, CC), 256>>>();
    g_kernel<<<CC, 256>>>();
    fin_kernel<<<1, 1>>>(out, out_size);
}

// round 17
// speedup vs baseline: 1.0670x; 1.0670x over previous
#include <cuda_runtime.h>
#include <cuda_bf16.h>
#include <math.h>
#include <stdint.h>

#ifndef M_PI
#define M_PI 3.14159265358979323846
#endif

#define BATCH 128
#define HH    256
#define CC    10
#define MATSZ (HH*HH)
#define DEG   9                   /* monomial degree; PS s=3: 4 matrix mults */

// ---- smem layout (bytes). 528-stride rows -> conflict-free ldmatrix. ----
#define YROW    528
#define YH_OFF  0
#define B_HI    135168            /* 256*528 */
#define B_LO    (B_HI + 64*528)
#define SMEM_TOTAL (B_HI + 2*64*528)      /* 202752 */

#define NTHR 512

// ---------------- scratch ----------------------------------------------------
__device__ __align__(16) __nv_bfloat16 g_Yh  [BATCH*MATSZ];
__device__ __align__(16) __nv_bfloat16 g_Yl  [BATCH*MATSZ];
__device__ __align__(16) __nv_bfloat16 g_Ylp [BATCH*MATSZ];   // fragment-major
__device__ __align__(16) __nv_bfloat16 g_Y2h [BATCH*MATSZ];
__device__ __align__(16) __nv_bfloat16 g_Y2l [BATCH*MATSZ];
__device__ __align__(16) __nv_bfloat16 g_Y3h [BATCH*MATSZ];
__device__ __align__(16) __nv_bfloat16 g_Y3l [BATCH*MATSZ];
__device__ __align__(16) __nv_bfloat16 g_Y3lp[BATCH*MATSZ];   // fragment-major
__device__ float g_B2[BATCH*MATSZ];   // a9*Y3 + a6 I + a7 Y + a8 Y2
__device__ float g_B1[BATCH*MATSZ];   // a3 I + a4 Y + a5 Y2
__device__ float g_B0[BATCH*MATSZ];   // a0 I + a1 Y + a2 Y2
__device__ float g_F [BATCH*MATSZ];
__device__ float g_Ws[CC*MATSZ];
__device__ float g_center[MATSZ];
__device__ float g_P [CC*MATSZ];
__device__ float g_acc;
__device__ int   g_done;

struct HArgs { float a[DEG+1]; };

// ---------------- PTX helpers ------------------------------------------------
__device__ __forceinline__ uint32_t smem_u32(const void* p) {
    uint32_t a;
    asm("{ .reg .u64 t; cvta.to.shared.u64 t, %1; cvt.u32.u64 %0, t; }"
        : "=r"(a) : "l"(p));
    return a;
}
__device__ __forceinline__ void cpasync16(uint32_t dst, const void* src) {
    asm volatile("cp.async.cg.shared.global [%0], [%1], 16;"
                 :: "r"(dst), "l"(src) : "memory");
}
__device__ __forceinline__ void cp_commit() {
    asm volatile("cp.async.commit_group;" ::: "memory");
}
template<int N> __device__ __forceinline__ void cp_wait() {
    asm volatile("cp.async.wait_group %0;" :: "n"(N) : "memory");
}
__device__ __forceinline__ void ldsm4(uint32_t& r0, uint32_t& r1,
                                      uint32_t& r2, uint32_t& r3, uint32_t a) {
    asm volatile("ldmatrix.sync.aligned.m8n8.x4.shared.b16 {%0,%1,%2,%3}, [%4];"
                 : "=r"(r0), "=r"(r1), "=r"(r2), "=r"(r3) : "r"(a));
}
__device__ __forceinline__ void mma16816(float* c, const uint32_t* a,
                                         uint32_t b0, uint32_t b1) {
    asm volatile(
        "mma.sync.aligned.m16n8k16.row.col.f32.bf16.bf16.f32 "
        "{%0,%1,%2,%3}, {%4,%5,%6,%7}, {%8,%9}, {%0,%1,%2,%3};"
        : "+f"(c[0]), "+f"(c[1]), "+f"(c[2]), "+f"(c[3])
        : "r"(a[0]), "r"(a[1]), "r"(a[2]), "r"(a[3]), "r"(b0), "r"(b1));
}
__device__ __forceinline__ uint32_t split2(float v0, float v1, uint32_t& lo) {
    __nv_bfloat16 h0 = __float2bfloat16(v0);
    __nv_bfloat16 l0 = __float2bfloat16(v0 - __bfloat162float(h0));
    __nv_bfloat16 h1 = __float2bfloat16(v1);
    __nv_bfloat16 l1 = __float2bfloat16(v1 - __bfloat162float(h1));
    lo = (uint32_t)__bfloat16_as_ushort(l0) | ((uint32_t)__bfloat16_as_ushort(l1) << 16);
    return (uint32_t)__bfloat16_as_ushort(h0) | ((uint32_t)__bfloat16_as_ushort(h1) << 16);
}
__device__ __forceinline__ float pair_sum(uint32_t h, uint32_t l, int sel) {
    unsigned short hu = sel ? (unsigned short)(h >> 16) : (unsigned short)(h & 0xffff);
    unsigned short lu = sel ? (unsigned short)(l >> 16) : (unsigned short)(l & 0xffff);
    return __bfloat162float(__ushort_as_bfloat16(hu)) +
           __bfloat162float(__ushort_as_bfloat16(lu));
}

// ---------------- shared mult k-loop (barrier-free, 16x64 warp tile) ---------
__device__ __forceinline__ void mult_kloop(
    const char* dsm, uint32_t aAhi, uint32_t aB,
    const uint4* __restrict__ Aperm, int w, int lane,
    float (&acc)[8][4])
{
    const int abase = w*32 + lane;
    uint4 av = __ldg(Aperm + abase);                  // kc = 0
    #pragma unroll 4
    for (int kc = 0; kc < 16; ++kc) {
        uint4 avn;
        if (kc < 15) avn = __ldg(Aperm + ((kc + 1)*512 + abase));
        const uint32_t kb = (uint32_t)(kc << 5);
        uint32_t ah[4], al[4];
        ldsm4(ah[0], ah[1], ah[2], ah[3], aAhi + kb);
        al[0] = av.x;  al[1] = av.y;  al[2] = av.z;  al[3] = av.w;
        #pragma unroll
        for (int np = 0; np < 4; ++np) {
            uint32_t a = aB + (uint32_t)(np*16*YROW) + kb;
            uint32_t bh0, bh1, bh2, bh3, bl0, bl1, bl2, bl3;
            ldsm4(bh0, bh1, bh2, bh3, a);
            ldsm4(bl0, bl1, bl2, bl3, a + (uint32_t)(64*YROW));
            mma16816(acc[2*np+0], ah, bh0, bh2);
            mma16816(acc[2*np+1], ah, bh1, bh3);
            mma16816(acc[2*np+0], ah, bl0, bl2);
            mma16816(acc[2*np+1], ah, bl1, bl3);
            mma16816(acc[2*np+0], al, bh0, bh2);
            mma16816(acc[2*np+1], al, bh1, bh3);
        }
        av = avn;
    }
}

// ---------------- prep: Y = s*X + o*I, split hi/lo (+ perm lo copy) ---------
__global__ void prep_mats(const float* __restrict__ X, float s, float o) {
    unsigned gid = blockIdx.x * blockDim.x + threadIdx.x;
    float4 x = ((const float4*)X)[gid];
    unsigned within = gid & (MATSZ/4 - 1);
    int i  = (int)(within >> 6);
    int j0 = (int)(within & 63) << 2;

    float y[4];
    y[0] = s*x.x + ((i==j0+0)?o:0.f);  y[1] = s*x.y + ((i==j0+1)?o:0.f);
    y[2] = s*x.z + ((i==j0+2)?o:0.f);  y[3] = s*x.w + ((i==j0+3)?o:0.f);

    unsigned hh[4], ll[4];
    #pragma unroll
    for (int q = 0; q < 4; ++q) {
        __nv_bfloat16 h = __float2bfloat16(y[q]);
        __nv_bfloat16 l = __float2bfloat16(y[q] - __bfloat162float(h));
        hh[q] = __bfloat16_as_ushort(h);
        ll[q] = __bfloat16_as_ushort(l);
    }
    uint32_t w0 = ll[0] | (ll[1]<<16);
    uint32_t w1 = ll[2] | (ll[3]<<16);
    ((uint2*)g_Yh)[gid] = make_uint2(hh[0] | (hh[1]<<16), hh[2] | (hh[3]<<16));
    ((uint2*)g_Yl)[gid] = make_uint2(w0, w1);

    // fragment-major copy of Y-lo
    {
        int m    = (int)(gid >> 14);            // matrix index (MATSZ/4 = 16384)
        int kc   = j0 >> 4;
        int band = i >> 4;
        int sub  = i & 7;
        int hi8  = (i >> 3) & 1;
        int khi  = (j0 >> 3) & 1;
        int lq0  = (j0 >> 1) & 3;               // even: 0 or 2
        int j    = hi8 + (khi << 1);
        uint32_t* Yp = (uint32_t*)g_Ylp + (size_t)m * (MATSZ/2);
        uint32_t base = (uint32_t)(((kc*16 + band)*32 + ((sub<<2) | lq0))*4 + j);
        Yp[base]     = w0;
        Yp[base + 4] = w1;                      // lq0+1 -> +4 words
    }
    if (gid == 0) { g_acc = 0.f; g_done = 0; }
}

__global__ void prep_W(const float* __restrict__ W) {
    int gid = blockIdx.x * blockDim.x + threadIdx.x;
    int c   = gid >> 16;
    int rem = gid & 65535;
    int i   = rem >> 8, j = rem & 255;
    g_Ws[gid] = 0.5f * (W[gid] + W[(c<<16) + (j<<8) + i]);
    if (gid < MATSZ) g_center[gid] = 0.f;       // zero for center atomics
}

// ---------------- pow phase: Y2 = Y*Y, Y3 = Y*Y2 -----------------------------
__global__ void __launch_bounds__(NTHR, 1) pow_kernel() {
    extern __shared__ char dsm[];
    const uint32_t sb = smem_u32(dsm);

    const int slice = blockIdx.x, b = blockIdx.y;
    const int tid = threadIdx.x, w = tid >> 5, lane = tid & 31;
    const int laneA = lane & 15, laneHi = (lane >> 4) << 4;
    const int n0g = slice << 6;
    const size_t moff = (size_t)b * MATSZ;
    const char* Yh = (const char*)(g_Yh + moff);

    // A resident = Yh; B init = Y[:, slice] (Y symmetric -> rows)
    #pragma unroll
    for (int i = 0; i < 16; ++i) {
        int op = tid + (i << 9);
        int r = op >> 5, ch = (op & 31) << 4;
        cpasync16(sb + YH_OFF + r*YROW + ch, Yh + r*512 + ch);
    }
    {
        const char* Yl = (const char*)(g_Yl + moff);
        #pragma unroll
        for (int i = 0; i < 4; ++i) {
            int op = tid + (i << 9);
            int n = op >> 5, ch = (op & 31) << 4;
            cpasync16(sb + B_HI + n*YROW + ch, Yh + (size_t)(n0g + n)*512 + ch);
            cpasync16(sb + B_LO + n*YROW + ch, Yl + (size_t)(n0g + n)*512 + ch);
        }
    }
    cp_commit();
    cp_wait<0>();
    __syncthreads();

    const uint32_t aAhi = sb + YH_OFF + (w*16 + laneA)*YROW + laneHi;
    const uint32_t aB   = sb + B_HI + laneA*YROW + laneHi;
    const uint4* Aperm  = (const uint4*)g_Ylp + (moff >> 3);

    #pragma unroll 1
    for (int step = 0; step < 2; ++step) {
        float acc[8][4];
        #pragma unroll
        for (int nt = 0; nt < 8; ++nt)
            #pragma unroll
            for (int q = 0; q < 4; ++q) acc[nt][q] = 0.f;

        mult_kloop(dsm, aAhi, aB, Aperm, w, lane, acc);
        __syncthreads();

        uint32_t* gh = (uint32_t*)((step == 0 ? g_Y2h : g_Y3h) + moff);
        uint32_t* gl = (uint32_t*)((step == 0 ? g_Y2l : g_Y3l) + moff);
        uint32_t* Yp = (uint32_t*)g_Y3lp + (moff >> 1);
        const bool toSmem = (step < 1);

        #pragma unroll
        for (int nt = 0; nt < 8; ++nt)
            #pragma unroll
            for (int hrow = 0; hrow < 2; ++hrow) {
                int r  = w*16 + (lane >> 2) + hrow*8;
                int c0 = nt*8 + ((lane & 3) << 1);
                float v0 = acc[nt][2*hrow], v1 = acc[nt][2*hrow+1];
                uint32_t lo, hi = split2(v0, v1, lo);
                uint32_t off = (uint32_t)(r*256 + n0g + c0);
                gh[off >> 1] = hi;
                gl[off >> 1] = lo;
                if (toSmem) {
                    *(uint16_t*)(dsm + B_HI + c0*YROW + r*2)     = (uint16_t)(hi & 0xffff);
                    *(uint16_t*)(dsm + B_HI + (c0+1)*YROW + r*2) = (uint16_t)(hi >> 16);
                    *(uint16_t*)(dsm + B_LO + c0*YROW + r*2)     = (uint16_t)(lo & 0xffff);
                    *(uint16_t*)(dsm + B_LO + (c0+1)*YROW + r*2) = (uint16_t)(lo >> 16);
                } else {
                    // fragment-major Y3-lo for horner's A operand
                    int slot = (((n0g >> 4) + (nt >> 1))*16 + w)*32 + lane;
                    Yp[slot*4 + (hrow + ((nt & 1) << 1))] = lo;
                }
            }
        __syncthreads();
    }
}

// ---------------- bterms: B2f / B1 / B0 (fp32, coalesced, once) -------------
__global__ void bterms_kernel(HArgs ha) {
    unsigned gid = blockIdx.x * blockDim.x + threadIdx.x;   // float4 group
    unsigned within = gid & (MATSZ/4 - 1);
    int i  = (int)(within >> 6);
    int j0 = (int)(within & 63) << 2;

    uint2 yh = ((const uint2*)g_Yh )[gid], yl = ((const uint2*)g_Yl )[gid];
    uint2 h2 = ((const uint2*)g_Y2h)[gid], l2 = ((const uint2*)g_Y2l)[gid];
    uint2 h3 = ((const uint2*)g_Y3h)[gid], l3 = ((const uint2*)g_Y3l)[gid];

    float b2[4], b1[4], b0[4];
    #pragma unroll
    for (int q = 0; q < 4; ++q) {
        int sel = q & 1;
        float y  = pair_sum(q < 2 ? yh.x : yh.y, q < 2 ? yl.x : yl.y, sel);
        float y2 = pair_sum(q < 2 ? h2.x : h2.y, q < 2 ? l2.x : l2.y, sel);
        float y3 = pair_sum(q < 2 ? h3.x : h3.y, q < 2 ? l3.x : l3.y, sel);
        float id = (i == j0 + q) ? 1.f : 0.f;
        b2[q] = ha.a[9]*y3 + ha.a[6]*id + ha.a[7]*y + ha.a[8]*y2;
        b1[q] = ha.a[3]*id + ha.a[4]*y + ha.a[5]*y2;
        b0[q] = ha.a[0]*id + ha.a[1]*y + ha.a[2]*y2;
    }
    ((float4*)g_B2)[gid] = make_float4(b2[0], b2[1], b2[2], b2[3]);
    ((float4*)g_B1)[gid] = make_float4(b1[0], b1[1], b1[2], b1[3]);
    ((float4*)g_B0)[gid] = make_float4(b0[0], b0[1], b0[2], b0[3]);
}

// ---------------- horner phase: C0 = B2f; C1 = Y3*C0 + B1; F = Y3*C1 + B0 ---
__global__ void __launch_bounds__(NTHR, 1) horner_kernel() {
    extern __shared__ char dsm[];
    const uint32_t sb = smem_u32(dsm);

    const int slice = blockIdx.x, b = blockIdx.y;
    const int tid = threadIdx.x, w = tid >> 5, lane = tid & 31;
    const int laneA = lane & 15, laneHi = (lane >> 4) << 4;
    const int n0g = slice << 6;
    const size_t moff = (size_t)b * MATSZ;

    // A resident = Y3 hi
    {
        const char* A = (const char*)(g_Y3h + moff);
        #pragma unroll
        for (int i = 0; i < 16; ++i) {
            int op = tid + (i << 9);
            int r = op >> 5, ch = (op & 31) << 4;
            cpasync16(sb + YH_OFF + r*YROW + ch, A + r*512 + ch);
        }
        cp_commit();
    }

    // C init: rows (n0g+nl) of C0 = B2f (coalesced fp32 load, split to bf16)
    {
        const float* B2 = g_B2 + moff;
        #pragma unroll 4
        for (int i = 0; i < 16; ++i) {
            int e  = tid + (i << 9);
            int nl = e >> 7;
            int k2 = (e & 127) << 1;
            float2 v = *(const float2*)(B2 + (size_t)(n0g + nl)*256 + k2);
            uint32_t lo, hi = split2(v.x, v.y, lo);
            *(uint32_t*)(dsm + B_HI + nl*YROW + k2*2) = hi;
            *(uint32_t*)(dsm + B_LO + nl*YROW + k2*2) = lo;
        }
    }
    cp_wait<0>();
    __syncthreads();

    const uint32_t aAhi = sb + YH_OFF + (w*16 + laneA)*YROW + laneHi;
    const uint32_t aB   = sb + B_HI + laneA*YROW + laneHi;
    const uint4* Aperm  = (const uint4*)g_Y3lp + (moff >> 3);

    // ---- mult 1: C1 = Y3*C0 + B1 ----
    {
        float acc[8][4];
        #pragma unroll
        for (int nt = 0; nt < 8; ++nt)
            #pragma unroll
            for (int q = 0; q < 4; ++q) acc[nt][q] = 0.f;
        mult_kloop(dsm, aAhi, aB, Aperm, w, lane, acc);
        __syncthreads();
        const float* B1 = g_B1 + moff;
        #pragma unroll
        for (int nt = 0; nt < 8; ++nt)
            #pragma unroll
            for (int hrow = 0; hrow < 2; ++hrow) {
                int r  = w*16 + (lane >> 2) + hrow*8;
                int c0 = nt*8 + ((lane & 3) << 1);
                float2 bv = *(const float2*)(B1 + (size_t)r*256 + n0g + c0);
                float v0 = acc[nt][2*hrow]   + bv.x;
                float v1 = acc[nt][2*hrow+1] + bv.y;
                uint32_t lo, hi = split2(v0, v1, lo);
                *(uint16_t*)(dsm + B_HI + c0*YROW + r*2)     = (uint16_t)(hi & 0xffff);
                *(uint16_t*)(dsm + B_HI + (c0+1)*YROW + r*2) = (uint16_t)(hi >> 16);
                *(uint16_t*)(dsm + B_LO + c0*YROW + r*2)     = (uint16_t)(lo & 0xffff);
                *(uint16_t*)(dsm + B_LO + (c0+1)*YROW + r*2) = (uint16_t)(lo >> 16);
            }
        __syncthreads();
    }

    // ---- mult 2: F = Y3*C1 + B0 (write gmem) ----
    {
        float acc[8][4];
        #pragma unroll
        for (int nt = 0; nt < 8; ++nt)
            #pragma unroll
            for (int q = 0; q < 4; ++q) acc[nt][q] = 0.f;
        mult_kloop(dsm, aAhi, aB, Aperm, w, lane, acc);

        const float* B0 = g_B0 + moff;
        float* Fm = g_F + moff;
        #pragma unroll
        for (int nt = 0; nt < 8; ++nt)
            #pragma unroll
            for (int hrow = 0; hrow < 2; ++hrow) {
                int r  = w*16 + (lane >> 2) + hrow*8;
                int c0 = nt*8 + ((lane & 3) << 1);
                float2 bv = *(const float2*)(B0 + (size_t)r*256 + n0g + c0);
                *(float2*)(Fm + (size_t)r*256 + n0g + c0) =
                    make_float2(acc[nt][2*hrow] + bv.x, acc[nt][2*hrow+1] + bv.y);
            }
    }
}

// ---------------- tails ------------------------------------------------------
__global__ void center_kernel() {
    int p  = blockIdx.x * blockDim.x + threadIdx.x;   // float2 index 0..32767
    int b0 = blockIdx.y << 5;                          // batch quarter * 32
    float sx = 0.f, sy = 0.f;
    #pragma unroll 4
    for (int i = 0; i < 32; ++i) {
        float2 v = ((const float2*)(g_F + (size_t)(b0 + i)*MATSZ))[p];
        sx += v.x;  sy += v.y;
    }
    const float inv = 1.f / BATCH;
    atomicAdd(&g_center[2*p],     sx * inv);
    atomicAdd(&g_center[2*p + 1], sy * inv);
}

// 64 blocks x 2 batches x 10 classes: Ws read 64x (192MB L2) vs 128x before
__global__ void out_kernel(float* __restrict__ out) {
    int b0 = blockIdx.x * 2;
    const float4* F0 = (const float4*)(g_F + (size_t)(b0+0)*MATSZ);
    const float4* F1 = (const float4*)(g_F + (size_t)(b0+1)*MATSZ);
    float acc[2][CC];
    #pragma unroll
    for (int j = 0; j < 2; ++j)
        #pragma unroll
        for (int c = 0; c < CC; ++c) acc[j][c] = 0.f;
    for (int t = threadIdx.x; t < MATSZ/4; t += 256) {
        float4 f0 = F0[t], f1 = F1[t];
        #pragma unroll
        for (int c = 0; c < CC; ++c) {
            float4 w = ((const float4*)(g_Ws + (size_t)c*MATSZ))[t];
            acc[0][c] += f0.x*w.x + f0.y*w.y + f0.z*w.z + f0.w*w.w;
            acc[1][c] += f1.x*w.x + f1.y*w.y + f1.z*w.z + f1.w*w.w;
        }
    }
    __shared__ float red[8][2][CC];
    #pragma unroll
    for (int j = 0; j < 2; ++j)
        #pragma unroll
        for (int c = 0; c < CC; ++c) {
            float v = acc[j][c];
            #pragma unroll
            for (int o = 16; o; o >>= 1) v += __shfl_down_sync(0xffffffffu, v, o);
            if ((threadIdx.x & 31) == 0) red[threadIdx.x >> 5][j][c] = v;
        }
    __syncthreads();
    if (threadIdx.x < 2*CC) {
        int j = threadIdx.x / CC, c = threadIdx.x % CC;
        float v = 0.f;
        #pragma unroll
        for (int w = 0; w < 8; ++w) v += red[w][j][c];
        out[(b0 + j)*CC + c] = v;
    }
}

__global__ void p_kernel() {
    int c  = blockIdx.y;
    int r0 = blockIdx.x * 32;
    __shared__ float Wb[32][256];
    for (int l = 0; l < 32; ++l)
        Wb[l][threadIdx.x] = g_Ws[(size_t)c*MATSZ + (size_t)(r0+l)*256 + threadIdx.x];
    __syncthreads();
    int j = threadIdx.x;
    float acc[32];
    #pragma unroll
    for (int ii = 0; ii < 32; ++ii) acc[ii] = 0.f;
    for (int k = 0; k < 256; ++k) {
        float bv = g_center[k*256 + j];
        #pragma unroll
        for (int ii = 0; ii < 32; ++ii) acc[ii] += Wb[ii][k] * bv;
    }
    for (int ii = 0; ii < 32; ++ii)
        g_P[(size_t)c*MATSZ + (size_t)(r0+ii)*256 + j] = acc[ii];
}

// g + fin fused: last block to finish writes the final output element
__global__ void g_kernel(float* __restrict__ out, int out_size) {
    int c = blockIdx.x;
    const float* P = g_P + (size_t)c*MATSZ;
    float acc = 0.f;
    for (int idx = threadIdx.x; idx < MATSZ; idx += 256) {
        int i = idx >> 8, j = idx & 255;
        acc += P[idx] * P[j*256 + i];
    }
    __shared__ float red[8];
    #pragma unroll
    for (int o = 16; o; o >>= 1) acc += __shfl_down_sync(0xffffffffu, acc, o);
    if ((threadIdx.x & 31) == 0) red[threadIdx.x >> 5] = acc;
    __syncthreads();
    if (threadIdx.x == 0) {
        float v = 0.f;
        #pragma unroll
        for (int w = 0; w < 8; ++w) v += red[w];
        atomicAdd(&g_acc, v);
        __threadfence();
        int old = atomicAdd(&g_done, 1);
        if (old == CC - 1)
            out[out_size - 1] = atomicAdd(&g_acc, 0.f) * (1.f / CC);
    }
}

// ---------------- host -------------------------------------------------------
extern "C" void kernel_launch(void* const* d_in, const int* in_sizes, int n_in,
                              void* d_out, int out_size) {
    const float* X = (const float*)d_in[0];
    const float* W = (const float*)d_in[1];
    float* out = (float*)d_out;

    const double a = 0.98, bb = 5.4;
    double coef[DEG+1];
    {
        const int N = 128;
        for (int k = 0; k <= DEG; ++k) {
            double s = 0.0;
            for (int j = 0; j < N; ++j) {
                double th  = M_PI * (j + 0.5) / N;
                double lam = 0.5*(bb+a) + 0.5*(bb-a)*cos(th);
                s += log(lam) * cos(k*th);
            }
            coef[k] = 2.0 / N * s;
        }
        coef[0] *= 0.5;
    }
    // Chebyshev -> monomial (safe: rho = 2.48 > 2)
    double tc[DEG+1][DEG+1] = {};
    tc[0][0] = 1.0;
    tc[1][1] = 1.0;
    for (int k = 2; k <= DEG; ++k)
        for (int j = 0; j <= k; ++j)
            tc[k][j] = (j ? 2.0*tc[k-1][j-1] : 0.0) - tc[k-2][j];
    double am[DEG+1] = {};
    for (int k = 0; k <= DEG; ++k)
        for (int j = 0; j <= k; ++j)
            am[j] += coef[k] * tc[k][j];

    const float sc = (float)( 2.0/(bb-a));
    const float of = (float)(-(bb+a)/(bb-a));
    HArgs ha;
    for (int j = 0; j <= DEG; ++j) ha.a[j] = (float)am[j];

    cudaFuncSetAttribute(pow_kernel,    cudaFuncAttributeMaxDynamicSharedMemorySize, SMEM_TOTAL);
    cudaFuncSetAttribute(horner_kernel, cudaFuncAttributeMaxDynamicSharedMemorySize, SMEM_TOTAL);

    // prep_W moved after horner (no consumer before center/out); makes
    // horner the 4th launch so ncu (-s skip) profiles it.
    prep_mats<<<(BATCH*MATSZ/4)/256, 256>>>(X, sc, of);
    pow_kernel<<<dim3(4, BATCH), NTHR, SMEM_TOTAL>>>();
    bterms_kernel<<<(BATCH*MATSZ/4)/256, 256>>>(ha);
    horner_kernel<<<dim3(4, BATCH), NTHR, SMEM_TOTAL>>>();
    prep_W<<<(CC*MATSZ)/256, 256>>>(W);
    center_kernel<<<dim3(128, 4), 256>>>();
    out_kernel<<<64, 256>>>(out);
    p_kernel<<<dim3(8, CC), 256>>>();
    g_kernel<<<CC, 256>>>(out, out_size);
}